// round 4
// baseline (speedup 1.0000x reference)
#include <cuda_runtime.h>
#include <cstdint>

// Problem constants
#define NB      2
#define N_SRC   131072
#define N_DST   131072
#define E_CNT   524288
#define FDIM    64
#define F4      (FDIM / 4)     // 16 float4 per feature row
#define EPS_F   1e-8f

#define SCAN_BLK   1024
#define SCAN_NBLK  (N_DST / SCAN_BLK)   // 128

// ---------------- scratch (__device__ globals; no allocation) ----------------
__device__ int   g_cnt[N_DST];      // edges per dst
__device__ int   g_cur[N_DST];      // fill cursor per dst
__device__ int   g_incl[N_DST];     // block-local inclusive scan of cnt
__device__ int   g_bsum[SCAN_NBLK]; // per-block totals
__device__ int   g_boff[SCAN_NBLK]; // exclusive scan of block totals
__device__ int   g_ssrc[E_CNT];     // src sorted by dst
__device__ float g_sw[E_CNT];       // weights sorted by dst

// ---------------------------------------------------------------------------
// K0: zero cnt + cur
// ---------------------------------------------------------------------------
__global__ void zero_kernel() {
    int i = blockIdx.x * blockDim.x + threadIdx.x;
    if (i < N_DST) { g_cnt[i] = 0; g_cur[i] = 0; }
}

// ---------------------------------------------------------------------------
// K1: histogram of dst  (int32 indices!)
// ---------------------------------------------------------------------------
__global__ void hist_kernel(const int* __restrict__ dst) {
    int e = blockIdx.x * blockDim.x + threadIdx.x;
    if (e < E_CNT) {
        int d = dst[e] & (N_DST - 1);   // clamp (power of 2): safety only
        atomicAdd(&g_cnt[d], 1);
    }
}

// ---------------------------------------------------------------------------
// K2: per-block inclusive scan of cnt (1024 elems/block, 128 blocks)
// ---------------------------------------------------------------------------
__global__ void scanA_kernel() {
    __shared__ int sh[SCAN_BLK];
    int tid = threadIdx.x;
    int i = blockIdx.x * SCAN_BLK + tid;
    sh[tid] = g_cnt[i];
    __syncthreads();
#pragma unroll
    for (int ofs = 1; ofs < SCAN_BLK; ofs <<= 1) {
        int t = (tid >= ofs) ? sh[tid - ofs] : 0;
        __syncthreads();
        sh[tid] += t;
        __syncthreads();
    }
    g_incl[i] = sh[tid];
    if (tid == SCAN_BLK - 1) g_bsum[blockIdx.x] = sh[tid];
}

// ---------------------------------------------------------------------------
// K3: exclusive scan of 128 block sums (single block)
// ---------------------------------------------------------------------------
__global__ void scanB_kernel() {
    __shared__ int sh[SCAN_NBLK];
    int tid = threadIdx.x;   // 0..127
    int v = g_bsum[tid];
    sh[tid] = v;
    __syncthreads();
#pragma unroll
    for (int ofs = 1; ofs < SCAN_NBLK; ofs <<= 1) {
        int t = (tid >= ofs) ? sh[tid - ofs] : 0;
        __syncthreads();
        sh[tid] += t;
        __syncthreads();
    }
    g_boff[tid] = sh[tid] - v;   // exclusive
}

__device__ __forceinline__ int dst_offset(int d) {
    // exclusive CSR offset of destination d
    return g_incl[d] - g_cnt[d] + g_boff[d >> 10];
}

// ---------------------------------------------------------------------------
// K4: fill CSR slots (src, w) sorted by dst
// ---------------------------------------------------------------------------
__global__ void fill_kernel(const int* __restrict__ src,
                            const int* __restrict__ dst,
                            const float* __restrict__ w) {
    int e = blockIdx.x * blockDim.x + threadIdx.x;
    if (e >= E_CNT) return;
    int d = dst[e] & (N_DST - 1);
    int s = src[e] & (N_SRC - 1);
    int pos = dst_offset(d) + atomicAdd(&g_cur[d], 1);
    if (pos >= 0 && pos < E_CNT) {
        g_ssrc[pos] = s;
        g_sw[pos]   = w[e];
    }
}

// ---------------------------------------------------------------------------
// K5: gather. One warp per dst. lane 0-15 -> batch0 float4 #lane,
// lane 16-31 -> batch1 float4 #(lane-16). Accumulate unnormalized sum in
// registers, scale once by 1/(sum_w + eps), single float4 store per lane.
// Empty rows store zeros (matches reference).
// ---------------------------------------------------------------------------
__global__ void gather_kernel(const float4* __restrict__ x4,
                              float4* __restrict__ out4) {
    int gtid = blockIdx.x * blockDim.x + threadIdx.x;
    int d    = gtid >> 5;
    int lane = gtid & 31;
    if (d >= N_DST) return;

    int beg = dst_offset(d);
    int n   = g_cnt[d];

    int b  = lane >> 4;
    int fi = lane & 15;
    const float4* xb = x4 + (size_t)b * N_SRC * F4 + fi;

    float4 acc = make_float4(0.f, 0.f, 0.f, 0.f);
    float  sumw = 0.f;

    // 2-stage pipeline on the broadcast (src, w) loads.
    int   s_nxt = 0;
    float w_nxt = 0.f;
    if (n > 0) { s_nxt = g_ssrc[beg]; w_nxt = g_sw[beg]; }

    for (int i = 0; i < n; i++) {
        int   s = s_nxt;
        float w = w_nxt;
        if (i + 1 < n) { s_nxt = g_ssrc[beg + i + 1]; w_nxt = g_sw[beg + i + 1]; }
        float4 v = xb[(size_t)s * F4];
        acc.x += w * v.x;
        acc.y += w * v.y;
        acc.z += w * v.z;
        acc.w += w * v.w;
        sumw  += w;
    }

    float inv = (n > 0) ? (1.0f / (sumw + EPS_F)) : 0.0f;
    float4 o = make_float4(acc.x * inv, acc.y * inv, acc.z * inv, acc.w * inv);
    out4[(size_t)b * N_DST * F4 + (size_t)d * F4 + fi] = o;
}

// ---------------------------------------------------------------------------
// Launch. Identify inputs by element count (robust to ordering):
//   x: 16,777,216 f32   edge_index: 1,048,576 i32   weights: 524,288 f32
// edge_index is [2, E] row-major: first E = src, next E = dst. Output f32.
// ---------------------------------------------------------------------------
extern "C" void kernel_launch(void* const* d_in, const int* in_sizes, int n_in,
                              void* d_out, int out_size) {
    const float* x   = nullptr;
    const int*   ei  = nullptr;
    const float* wts = nullptr;

    for (int i = 0; i < n_in; i++) {
        if (in_sizes[i] == NB * N_SRC * FDIM)      x   = (const float*)d_in[i];
        else if (in_sizes[i] == 2 * E_CNT)         ei  = (const int*)d_in[i];
        else if (in_sizes[i] == E_CNT)             wts = (const float*)d_in[i];
    }
    // Fallback to metadata order if counts didn't match
    if (!x)   x   = (const float*)d_in[0];
    if (!ei)  ei  = (const int*)d_in[1];
    if (!wts) wts = (const float*)d_in[2];

    const int* src = ei;
    const int* dst = ei + E_CNT;
    float* out = (float*)d_out;

    zero_kernel<<<(N_DST + 255) / 256, 256>>>();
    hist_kernel<<<(E_CNT + 255) / 256, 256>>>(dst);
    scanA_kernel<<<SCAN_NBLK, SCAN_BLK>>>();
    scanB_kernel<<<1, SCAN_NBLK>>>();
    fill_kernel<<<(E_CNT + 255) / 256, 256>>>(src, dst, wts);

    {
        // one warp per dst: N_DST warps, 8 warps per 256-thread block
        long long total_threads = (long long)N_DST * 32;
        int threads = 256;
        int blocks = (int)((total_threads + threads - 1) / threads);
        gather_kernel<<<blocks, threads>>>((const float4*)x, (float4*)out);
    }
}